// round 1
// baseline (speedup 1.0000x reference)
#include <cuda_runtime.h>

// ---------------------------------------------------------------------------
// CapsuleNetwork forward on GB300 (sm_103a), fp32, FFMA2 (f32x2) inner loops.
//
// Pipeline (7 launches):
//  1. repack_w1 : conv1_w (c,81) -> w1t (81,256)             [k-major for LDS]
//  2. repack_wp : pc_w (n,c,81)  -> wpt (c,81,256)           [k-major, coalesced tiles]
//  3. conv1     : x(256,1,28,28) -> h(256,256,20,20) relu    [per-image, smem weights]
//  4. pc_gemm   : h -> p(256,256,6,6)  implicit GEMM         [M=36/img, N=128 tile, K=20736]
//  5. squash    : p -> u(256,1152,8)
//  6. uhat      : u x W_digit -> u_hat(256,1152,160)
//  7. routing   : 3 dynamic-routing iters fused per image -> v(256,10,16)
// ---------------------------------------------------------------------------

#define NB    256      // batch
#define NC1   256      // conv1 channels
#define HW1   400      // 20*20
#define NPRI  1152     // primary capsules
#define CDIM  8
#define NOUT  10
#define ODIM  16
#define JO    160      // NOUT*ODIM

// ------------------------------- scratch -----------------------------------
__device__ float g_w1t[81 * 256];                       // (k, c)
__device__ float g_wpt[256 * 81 * 256];                 // (c, k, n)   21.2 MB
__device__ float g_h  [NB * NC1 * HW1];                 // 104.9 MB
__device__ float g_p  [NB * 256 * 36];                  // 9.4 MB
__device__ float g_u  [NB * NPRI * CDIM];               // 9.4 MB
__device__ float g_uhat[NB * NPRI * JO];                // 188.7 MB

// ------------------------------ f32x2 helpers ------------------------------
__device__ __forceinline__ unsigned long long pk2(float lo, float hi) {
    unsigned long long r;
    asm("mov.b64 %0, {%1, %2};" : "=l"(r) : "f"(lo), "f"(hi));
    return r;
}
__device__ __forceinline__ void upk2(unsigned long long v, float& lo, float& hi) {
    asm("mov.b64 {%0, %1}, %2;" : "=f"(lo), "=f"(hi) : "l"(v));
}
__device__ __forceinline__ void fma2(unsigned long long& d,
                                     unsigned long long a, unsigned long long b) {
    asm("fma.rn.f32x2 %0, %1, %2, %0;" : "+l"(d) : "l"(a), "l"(b));
}

// ------------------------------ repacks ------------------------------------
__global__ void repack_w1_kernel(const float* __restrict__ w) {
    int k = blockIdx.x;       // 0..80
    int c = threadIdx.x;      // 0..255
    g_w1t[k * 256 + c] = w[c * 81 + k];
}

__global__ void repack_wp_kernel(const float* __restrict__ w) {
    int c = blockIdx.x;       // 0..255 (input channel)
    int n = threadIdx.x;      // 0..255 (output channel)
    const float* src = w + (size_t)n * 20736 + c * 81;
    float* dst = g_wpt + (size_t)c * 20736 + n;
    #pragma unroll 3
    for (int k = 0; k < 81; k++) dst[k * 256] = src[k];
}

// ------------------------------ conv1 --------------------------------------
// grid 512 = (b, ch-half).  block 256 = (tx 0..15 -> 8 ch of 128, ty 0..15 -> 25 pos)
template<int NP>
__device__ __forceinline__ void conv1_tile(const float* __restrict__ ws,
                                           const float* __restrict__ xs,
                                           const float* __restrict__ bias,
                                           int b, int h0, int tx, int ty, int chunk) {
    int idx[NP], posA[NP];
    #pragma unroll
    for (int p = 0; p < NP; p++) {
        int pos = ty + 16 * (chunk * 10 + p);
        posA[p] = pos;
        idx[p] = (pos / 20) * 28 + (pos % 20);
    }
    unsigned long long acc[NP][4];
    #pragma unroll
    for (int p = 0; p < NP; p++)
        #pragma unroll
        for (int q = 0; q < 4; q++) acc[p][q] = 0ull;

    for (int ky = 0; ky < 9; ky++) {
        for (int kx = 0; kx < 9; kx++) {
            int k = ky * 9 + kx;
            float4 wa = ((const float4*)ws)[k * 32 + tx];
            float4 wb = ((const float4*)ws)[k * 32 + 16 + tx];
            unsigned long long w0 = pk2(wa.x, wa.y), w1 = pk2(wa.z, wa.w);
            unsigned long long w2 = pk2(wb.x, wb.y), w3 = pk2(wb.z, wb.w);
            int off = ky * 28 + kx;
            #pragma unroll
            for (int p = 0; p < NP; p++) {
                float xv = xs[idx[p] + off];
                unsigned long long xx = pk2(xv, xv);
                fma2(acc[p][0], w0, xx);
                fma2(acc[p][1], w1, xx);
                fma2(acc[p][2], w2, xx);
                fma2(acc[p][3], w3, xx);
            }
        }
    }
    // store with bias + relu
    #pragma unroll
    for (int p = 0; p < NP; p++) {
        int pos = posA[p];
        #pragma unroll
        for (int q = 0; q < 4; q++) {
            float lo, hi; upk2(acc[p][q], lo, hi);
            int ch = (q < 2) ? (h0 + tx * 4 + 2 * q) : (h0 + 64 + tx * 4 + 2 * (q - 2));
            int bi = 2 * q;
            float v0 = fmaxf(lo + bias[bi], 0.f);
            float v1 = fmaxf(hi + bias[bi + 1], 0.f);
            g_h[(b * 256 + ch) * HW1 + pos]       = v0;
            g_h[(b * 256 + ch + 1) * HW1 + pos]   = v1;
        }
    }
}

__global__ __launch_bounds__(256, 2)
void conv1_kernel(const float* __restrict__ x, const float* __restrict__ b1) {
    __shared__ float ws[81 * 128];
    __shared__ float xs[784];
    int bx = blockIdx.x;
    int b  = bx >> 1;
    int h0 = (bx & 1) << 7;          // 0 or 128
    int tid = threadIdx.x;

    {
        float4* wd = (float4*)ws;
        for (int e = tid; e < 81 * 32; e += 256) {
            int k = e >> 5, v = e & 31;
            wd[e] = ((const float4*)g_w1t)[k * 64 + (h0 >> 2) + v];
        }
        float4* xd = (float4*)xs;
        const float4* xsrc = (const float4*)(x + b * 784);
        for (int e = tid; e < 196; e += 256) xd[e] = xsrc[e];
    }
    __syncthreads();

    int tx = tid & 15, ty = tid >> 4;
    float bias[8];
    #pragma unroll
    for (int cc = 0; cc < 4; cc++) {
        bias[cc]     = b1[h0 + tx * 4 + cc];
        bias[4 + cc] = b1[h0 + 64 + tx * 4 + cc];
    }
    conv1_tile<10>(ws, xs, bias, b, h0, tx, ty, 0);
    conv1_tile<10>(ws, xs, bias, b, h0, tx, ty, 1);
    conv1_tile<5 >(ws, xs, bias, b, h0, tx, ty, 2);
}

// ------------------------------ pc_gemm ------------------------------------
// grid 512 = (b, n-tile).  block 192 = (tx 0..31 -> 4 n, oy 0..5)
// acc[ox][2 x f32x2]  (6 ox * 4 n = 24 outputs/thread)
__global__ __launch_bounds__(192, 3)
void pc_gemm_kernel(const float* __restrict__ pcb) {
    __shared__ float ws[81 * 128];   // (k, n) tile
    __shared__ float hs[400];        // one input channel of one image
    int bx = blockIdx.x;
    int b = bx >> 1, nt = bx & 1;
    int tid = threadIdx.x, tx = tid & 31, oy = tid >> 5;

    unsigned long long acc[6][2];
    #pragma unroll
    for (int ox = 0; ox < 6; ox++) { acc[ox][0] = 0ull; acc[ox][1] = 0ull; }

    const float4* wsrc = (const float4*)g_wpt;
    const float4* hsrc = (const float4*)(g_h + (size_t)b * 256 * HW1);

    for (int c = 0; c < 256; c++) {
        __syncthreads();
        if (tid < 100) ((float4*)hs)[tid] = hsrc[c * 100 + tid];
        for (int e = tid; e < 81 * 32; e += 192) {
            int k = e >> 5, v = e & 31;
            ((float4*)ws)[e] = wsrc[(c * 81 + k) * 64 + (nt << 5) + v];
        }
        __syncthreads();

        for (int ky = 0; ky < 9; ky++) {
            const float4* hr4 = (const float4*)(hs + (2 * oy + ky) * 20);
            unsigned long long hx[20];
            #pragma unroll
            for (int q = 0; q < 5; q++) {
                float4 t4 = hr4[q];
                hx[4 * q + 0] = pk2(t4.x, t4.x);
                hx[4 * q + 1] = pk2(t4.y, t4.y);
                hx[4 * q + 2] = pk2(t4.z, t4.z);
                hx[4 * q + 3] = pk2(t4.w, t4.w);
            }
            #pragma unroll
            for (int kx = 0; kx < 9; kx++) {
                float4 w4 = ((const float4*)ws)[(ky * 9 + kx) * 32 + tx];
                unsigned long long w0 = pk2(w4.x, w4.y), w1 = pk2(w4.z, w4.w);
                #pragma unroll
                for (int ox = 0; ox < 6; ox++) {
                    fma2(acc[ox][0], w0, hx[2 * ox + kx]);
                    fma2(acc[ox][1], w1, hx[2 * ox + kx]);
                }
            }
        }
    }

    int nb = (nt << 7) + tx * 4;
    float b0 = pcb[nb], b1v = pcb[nb + 1], b2 = pcb[nb + 2], b3 = pcb[nb + 3];
    #pragma unroll
    for (int ox = 0; ox < 6; ox++) {
        float v0, v1, v2, v3;
        upk2(acc[ox][0], v0, v1); upk2(acc[ox][1], v2, v3);
        int s = oy * 6 + ox;
        float* pp = g_p + ((size_t)b * 256 + nb) * 36 + s;
        pp[0]      = v0 + b0;
        pp[36]     = v1 + b1v;
        pp[72]     = v2 + b2;
        pp[108]    = v3 + b3;
    }
}

// ------------------------------ squash primary -----------------------------
__global__ void squash_kernel() {
    int idx = blockIdx.x * 256 + threadIdx.x;   // = b*1152 + i, 0..294911
    int b = idx / NPRI, i = idx % NPRI;
    int cap = i / 36, s = i % 36;
    const float* pp = g_p + ((size_t)b * 256 + cap * 8) * 36 + s;
    float v[8]; float sq = 0.f;
    #pragma unroll
    for (int d = 0; d < 8; d++) { v[d] = pp[d * 36]; sq += v[d] * v[d]; }
    float coef = sq / ((1.f + sq) * sqrtf(sq + 1e-8f));
    float* up = g_u + (size_t)idx * 8;
    #pragma unroll
    for (int d = 0; d < 8; d++) up[d] = coef * v[d];
}

// ------------------------------ u_hat --------------------------------------
// grid (1152, 8), block 320 = 2 x 160.  Each block does 32 images for one i.
__global__ void uhat_kernel(const float* __restrict__ W) {
    __shared__ float Ws[8 * JO];
    int i = blockIdx.x, bgrp = blockIdx.y;
    int tid = threadIdx.x;
    for (int e = tid; e < 8 * JO; e += 320) Ws[e] = W[(size_t)i * 1280 + e];
    __syncthreads();
    int t = tid % JO, g = tid / JO;
    for (int bb = 0; bb < 16; bb++) {
        int b = bgrp * 32 + bb * 2 + g;
        const float* up = g_u + ((size_t)b * NPRI + i) * 8;
        float a = 0.f;
        #pragma unroll
        for (int d = 0; d < 8; d++) a += up[d] * Ws[d * JO + t];
        g_uhat[((size_t)b * NPRI + i) * JO + t] = a;
    }
}

// ------------------------------ routing ------------------------------------
// grid 256 (one image/block), block 480 = 3 x 160.
// smem: logits(11520) + coupling(11520) + sred(480) + v(160) = 94720 B
__global__ void routing_kernel(float* __restrict__ out) {
    extern __shared__ float sm[];
    float* l    = sm;              // 11520
    float* cpl  = sm + 11520;      // 11520
    float* sred = sm + 23040;      // 480
    float* v    = sm + 23520;      // 160

    int b = blockIdx.x, tid = threadIdx.x;
    for (int e = tid; e < 11520; e += 480) l[e] = 0.f;
    __syncthreads();

    const float* uh = g_uhat + (size_t)b * NPRI * JO;
    int t = tid % JO, g = tid / JO;
    int j = t >> 4;

    for (int it = 0; it < 3; it++) {
        // softmax over j for every primary capsule row
        for (int row = tid; row < NPRI; row += 480) {
            float lv[10]; float m = -1e30f;
            #pragma unroll
            for (int jj = 0; jj < 10; jj++) { lv[jj] = l[row * 10 + jj]; m = fmaxf(m, lv[jj]); }
            float sum = 0.f;
            #pragma unroll
            for (int jj = 0; jj < 10; jj++) { lv[jj] = __expf(lv[jj] - m); sum += lv[jj]; }
            float r = 1.f / sum;
            #pragma unroll
            for (int jj = 0; jj < 10; jj++) cpl[row * 10 + jj] = lv[jj] * r;
        }
        __syncthreads();

        // s = sum_i c[i,j] * u_hat[i,j,o]  (3-way split over i)
        float s0 = 0.f, s1 = 0.f, s2 = 0.f, s3 = 0.f;
        int i0 = g * 384;
        for (int i = i0; i < i0 + 384; i += 4) {
            s0 += cpl[(i + 0) * 10 + j] * uh[(i + 0) * JO + t];
            s1 += cpl[(i + 1) * 10 + j] * uh[(i + 1) * JO + t];
            s2 += cpl[(i + 2) * 10 + j] * uh[(i + 2) * JO + t];
            s3 += cpl[(i + 3) * 10 + j] * uh[(i + 3) * JO + t];
        }
        sred[g * JO + t] = (s0 + s1) + (s2 + s3);
        __syncthreads();

        if (tid < JO) {
            float s = sred[t] + sred[JO + t] + sred[2 * JO + t];
            float sq = s * s;
            #pragma unroll
            for (int msk = 8; msk >= 1; msk >>= 1)
                sq += __shfl_xor_sync(0xffffffff, sq, msk);
            float coef = sq / ((1.f + sq) * sqrtf(sq + 1e-8f));
            float vv = coef * s;
            v[t] = vv;
            if (it == 2) out[b * JO + t] = vv;
        }
        __syncthreads();

        if (it < 2) {
            // agreement: l[i,j] += dot16(u_hat[i,j,:], v[j,:])
            for (int pr = tid; pr < 11520; pr += 480) {
                int i = pr / 10, jj = pr % 10;
                const float* up = uh + i * JO + jj * 16;
                const float* vp = v + jj * 16;
                float dot = 0.f;
                #pragma unroll
                for (int o = 0; o < 16; o++) dot += up[o] * vp[o];
                l[pr] += dot;
            }
            __syncthreads();
        }
    }
}

// ------------------------------ launch -------------------------------------
extern "C" void kernel_launch(void* const* d_in, const int* in_sizes, int n_in,
                              void* d_out, int out_size) {
    const float *x = nullptr, *w1 = nullptr, *b1 = nullptr;
    const float *wp = nullptr, *bp = nullptr, *Wd = nullptr;
    int n256 = 0;
    for (int i = 0; i < n_in; i++) {
        int s = in_sizes[i];
        const float* p = (const float*)d_in[i];
        if      (s == 200704)  x  = p;
        else if (s == 20736)   w1 = p;
        else if (s == 5308416) wp = p;
        else if (s == 1474560) Wd = p;
        else if (s == 256) { if (n256 == 0) b1 = p; else bp = p; n256++; }
    }
    // positional fallback
    if (!x  && n_in > 0) x  = (const float*)d_in[0];
    if (!w1 && n_in > 1) w1 = (const float*)d_in[1];
    if (!b1 && n_in > 2) b1 = (const float*)d_in[2];
    if (!wp && n_in > 3) wp = (const float*)d_in[3];
    if (!bp && n_in > 4) bp = (const float*)d_in[4];
    if (!Wd && n_in > 5) Wd = (const float*)d_in[5];

    cudaFuncSetAttribute(routing_kernel,
                         cudaFuncAttributeMaxDynamicSharedMemorySize, 94720);

    repack_w1_kernel<<<81, 256>>>(w1);
    repack_wp_kernel<<<256, 256>>>(wp);
    conv1_kernel<<<512, 256>>>(x, b1);
    pc_gemm_kernel<<<512, 192>>>(bp);
    squash_kernel<<<1152, 256>>>();
    uhat_kernel<<<dim3(1152, 8), 320>>>(Wd);
    routing_kernel<<<256, 480, 94720>>>((float*)d_out);
}

// round 3
// speedup vs baseline: 1.8850x; 1.8850x over previous
#include <cuda_runtime.h>
#include <cuda_fp16.h>
#include <cstdint>

// ---------------------------------------------------------------------------
// CapsuleNetwork forward, GB300 sm_103a — baseline-PTX tensor cores.
// (harness PTX target is family-agnostic compute_103: no tcgen05; use
//  ldmatrix + mma.sync.m16n8k16.f16 + cp.async, which are baseline ISA)
//
// Launches:
//  1. repack_w1 : conv1_w (c,81) -> w1t (81,256)
//  2. wsplit    : pc_w (n,c,81)  -> W hi/lo fp16 [81][outch][c]
//  3. conv1     : x -> h[b][c][400] fp32 relu         [SIMT f32x2, proven]
//  4. hsplit    : h -> H hi/lo fp16 [pos 400][b][c]   [transpose + split]
//  5. caps_gemm : mma.sync 128x128x32 tiles, fp16 split (3 MMAs) -> p
//  6. squash    : p + bias -> u [i][b][8]
//  7. uhat      : u x W_digit -> u_hat (B,1152,160)
//  8. routing   : 3 routing iters fused per image -> v
// ---------------------------------------------------------------------------

#define NB    256
#define HW1   400
#define NPRI  1152
#define JO    160

// ------------------------------- scratch -----------------------------------
__device__ float g_w1t[81 * 256];
__device__ float g_h  [(size_t)NB * 256 * HW1];            // 104.9 MB
__device__ __half g_hh[(size_t)400 * 256 * 256];           // 52.4 MB
__device__ __half g_hl[(size_t)400 * 256 * 256];           // 52.4 MB
__device__ __half g_wh[(size_t)81 * 256 * 256];            // 10.6 MB
__device__ __half g_wl[(size_t)81 * 256 * 256];            // 10.6 MB
__device__ float g_p  [(size_t)36 * 256 * 256];            // 9.4 MB  [pos][m][b]
__device__ float g_u  [(size_t)NPRI * 256 * 8];            // 9.4 MB  [i][b][d]
__device__ float g_uhat[(size_t)NB * NPRI * JO];           // 188.7 MB

// ------------------------------ ptx helpers --------------------------------
__device__ __forceinline__ uint32_t smem_u32(const void* p) {
    uint32_t a;
    asm("{ .reg .u64 t; cvta.to.shared.u64 t, %1; cvt.u32.u64 %0, t; }"
        : "=r"(a) : "l"(p));
    return a;
}
__device__ __forceinline__ void cpasync16(uint32_t s, const void* g) {
    asm volatile("cp.async.cg.shared.global [%0], [%1], 16;" :: "r"(s), "l"(g));
}
__device__ __forceinline__ void cp_commit() {
    asm volatile("cp.async.commit_group;" ::: "memory");
}
template<int N> __device__ __forceinline__ void cp_wait() {
    asm volatile("cp.async.wait_group %0;" :: "n"(N) : "memory");
}
__device__ __forceinline__ void ldm4(uint32_t* r, uint32_t a) {
    asm volatile("ldmatrix.sync.aligned.m8n8.x4.shared.b16 {%0,%1,%2,%3}, [%4];"
                 : "=r"(r[0]), "=r"(r[1]), "=r"(r[2]), "=r"(r[3]) : "r"(a));
}
__device__ __forceinline__ void mma16816(float* c, const uint32_t* a,
                                         const uint32_t* b) {
    asm volatile(
        "mma.sync.aligned.m16n8k16.row.col.f32.f16.f16.f32 "
        "{%0,%1,%2,%3}, {%4,%5,%6,%7}, {%8,%9}, {%0,%1,%2,%3};"
        : "+f"(c[0]), "+f"(c[1]), "+f"(c[2]), "+f"(c[3])
        : "r"(a[0]), "r"(a[1]), "r"(a[2]), "r"(a[3]), "r"(b[0]), "r"(b[1]));
}

// ------------------------------ f32x2 helpers ------------------------------
__device__ __forceinline__ unsigned long long pk2(float lo, float hi) {
    unsigned long long r;
    asm("mov.b64 %0, {%1, %2};" : "=l"(r) : "f"(lo), "f"(hi));
    return r;
}
__device__ __forceinline__ void upk2(unsigned long long v, float& lo, float& hi) {
    asm("mov.b64 {%0, %1}, %2;" : "=f"(lo), "=f"(hi) : "l"(v));
}
__device__ __forceinline__ void fma2(unsigned long long& d,
                                     unsigned long long a, unsigned long long b) {
    asm("fma.rn.f32x2 %0, %1, %2, %0;" : "+l"(d) : "l"(a), "l"(b));
}

// ------------------------------ repacks ------------------------------------
__global__ void repack_w1_kernel(const float* __restrict__ w) {
    int k = blockIdx.x, c = threadIdx.x;
    g_w1t[k * 256 + c] = w[c * 81 + k];
}

__global__ void wsplit_kernel(const float* __restrict__ w) {
    int n = blockIdx.x, c = threadIdx.x;   // n = outch, c = inch
    const float* src = w + ((size_t)n * 256 + c) * 81;
    for (int k = 0; k < 81; k++) {
        float v = src[k];
        __half hi = __float2half_rn(v);
        __half lo = __float2half_rn(v - __half2float(hi));
        size_t o = ((size_t)k * 256 + n) * 256 + c;
        g_wh[o] = hi; g_wl[o] = lo;
    }
}

// ------------------------------ conv1 (proven) -----------------------------
template<int NP>
__device__ __forceinline__ void conv1_tile(const float* __restrict__ ws,
                                           const float* __restrict__ xs,
                                           const float* __restrict__ bias,
                                           int b, int h0, int tx, int ty, int chunk) {
    int idx[NP], posA[NP];
    #pragma unroll
    for (int p = 0; p < NP; p++) {
        int pos = ty + 16 * (chunk * 10 + p);
        posA[p] = pos;
        idx[p] = (pos / 20) * 28 + (pos % 20);
    }
    unsigned long long acc[NP][4];
    #pragma unroll
    for (int p = 0; p < NP; p++)
        #pragma unroll
        for (int q = 0; q < 4; q++) acc[p][q] = 0ull;

    for (int ky = 0; ky < 9; ky++) {
        for (int kx = 0; kx < 9; kx++) {
            int k = ky * 9 + kx;
            float4 wa = ((const float4*)ws)[k * 32 + tx];
            float4 wb = ((const float4*)ws)[k * 32 + 16 + tx];
            unsigned long long w0 = pk2(wa.x, wa.y), w1 = pk2(wa.z, wa.w);
            unsigned long long w2 = pk2(wb.x, wb.y), w3 = pk2(wb.z, wb.w);
            int off = ky * 28 + kx;
            #pragma unroll
            for (int p = 0; p < NP; p++) {
                float xv = xs[idx[p] + off];
                unsigned long long xx = pk2(xv, xv);
                fma2(acc[p][0], w0, xx);
                fma2(acc[p][1], w1, xx);
                fma2(acc[p][2], w2, xx);
                fma2(acc[p][3], w3, xx);
            }
        }
    }
    #pragma unroll
    for (int p = 0; p < NP; p++) {
        int pos = posA[p];
        #pragma unroll
        for (int q = 0; q < 4; q++) {
            float lo, hi; upk2(acc[p][q], lo, hi);
            int ch = (q < 2) ? (h0 + tx * 4 + 2 * q) : (h0 + 64 + tx * 4 + 2 * (q - 2));
            int bi = 2 * q;
            float v0 = fmaxf(lo + bias[bi], 0.f);
            float v1 = fmaxf(hi + bias[bi + 1], 0.f);
            g_h[((size_t)b * 256 + ch) * HW1 + pos]     = v0;
            g_h[((size_t)b * 256 + ch + 1) * HW1 + pos] = v1;
        }
    }
}

__global__ __launch_bounds__(256, 2)
void conv1_kernel(const float* __restrict__ x, const float* __restrict__ b1) {
    __shared__ float ws[81 * 128];
    __shared__ float xs[784];
    int bx = blockIdx.x;
    int b  = bx >> 1;
    int h0 = (bx & 1) << 7;
    int tid = threadIdx.x;
    {
        float4* wd = (float4*)ws;
        for (int e = tid; e < 81 * 32; e += 256) {
            int k = e >> 5, v = e & 31;
            wd[e] = ((const float4*)g_w1t)[k * 64 + (h0 >> 2) + v];
        }
        float4* xd = (float4*)xs;
        const float4* xsrc = (const float4*)(x + b * 784);
        for (int e = tid; e < 196; e += 256) xd[e] = xsrc[e];
    }
    __syncthreads();
    int tx = tid & 15, ty = tid >> 4;
    float bias[8];
    #pragma unroll
    for (int cc = 0; cc < 4; cc++) {
        bias[cc]     = b1[h0 + tx * 4 + cc];
        bias[4 + cc] = b1[h0 + 64 + tx * 4 + cc];
    }
    conv1_tile<10>(ws, xs, bias, b, h0, tx, ty, 0);
    conv1_tile<10>(ws, xs, bias, b, h0, tx, ty, 1);
    conv1_tile<5 >(ws, xs, bias, b, h0, tx, ty, 2);
}

// ------------------- h transpose + fp16 hi/lo split ------------------------
// g_h[b][c][pos] -> g_hh/g_hl[pos][b][c]
__global__ void hsplit_kernel() {
    __shared__ float t[32][33];
    int b = blockIdx.z, c0 = blockIdx.y * 32, p0 = blockIdx.x * 32;
    int tx = threadIdx.x, ty = threadIdx.y;      // 32 x 8
    const float* src = g_h + ((size_t)b * 256 + c0) * HW1 + p0;
    #pragma unroll
    for (int r = 0; r < 4; r++) {
        if (p0 + tx < HW1) t[ty + r * 8][tx] = src[(ty + r * 8) * HW1 + tx];
    }
    __syncthreads();
    #pragma unroll
    for (int r = 0; r < 4; r++) {
        int p = p0 + ty + r * 8;
        if (p < HW1) {
            float v = t[tx][ty + r * 8];
            __half hi = __float2half_rn(v);
            __half lo = __float2half_rn(v - __half2float(hi));
            size_t o = ((size_t)p * 256 + b) * 256 + c0 + tx;
            g_hh[o] = hi; g_hl[o] = lo;
        }
    }
}

// ------------------------------ caps_gemm ----------------------------------
// grid 144 = 36 pos x 2 mt x 2 nt.  CTA tile M128(outch) x N128(batch), K=32/stage,
// 648 stages (81 koff x 8 c-chunks).  8 warps 4(M)x2(N), warp tile 32x64.
// fp16 hi/lo split: acc += Ah*Bh + Ah*Bl + Al*Bh.
// smem/stage 32KB: Ahi Alo Bhi Blo (128 rows x 64B, swizzle u^=(row>>1)&3).
__device__ __forceinline__ uint32_t swz(int row, int u) {
    return (uint32_t)(row * 64 + ((u ^ ((row >> 1) & 3)) * 16));
}

__device__ __forceinline__ void load_stage(int s, uint32_t sbase,
                                           int pos, int mt, int nt, int tid) {
    int koff = s >> 3, c0 = (s & 7) * 32;
    int ky = koff / 9, kx = koff - ky * 9;
    int oy = pos / 6, ox = pos % 6;
    int plin = (2 * oy + ky) * 20 + (2 * ox + kx);
    int row = tid >> 1;
    int u0 = (tid & 1) * 2;
    size_t aoff = ((size_t)(koff * 256 + mt * 128 + row)) * 256 + c0;
    size_t boff = ((size_t)(plin * 256 + nt * 128 + row)) * 256 + c0;
    #pragma unroll
    for (int uu = 0; uu < 2; uu++) {
        int u = u0 + uu;
        uint32_t so = swz(row, u);
        cpasync16(sbase + so,         g_wh + aoff + u * 8);
        cpasync16(sbase + 8192 + so,  g_wl + aoff + u * 8);
        cpasync16(sbase + 16384 + so, g_hh + boff + u * 8);
        cpasync16(sbase + 24576 + so, g_hl + boff + u * 8);
    }
}

__global__ __launch_bounds__(256, 1)
void caps_gemm_kernel() {
    extern __shared__ __align__(1024) char smem[];
    uint32_t sb = smem_u32(smem);

    int tid = threadIdx.x, lane = tid & 31, wid = tid >> 5;
    int wm = wid >> 1, wn = wid & 1;
    int bid = blockIdx.x;
    int pos = bid >> 2, mt = (bid >> 1) & 1, nt = bid & 1;

    float acc[2][8][4];
    #pragma unroll
    for (int mi = 0; mi < 2; mi++)
        #pragma unroll
        for (int ni = 0; ni < 8; ni++)
            #pragma unroll
            for (int q = 0; q < 4; q++) acc[mi][ni][q] = 0.f;

    load_stage(0, sb, pos, mt, nt, tid);
    cp_commit();

    for (int s = 0; s < 648; s++) {
        int buf = s & 1;
        if (s + 1 < 648) {
            load_stage(s + 1, sb + (buf ^ 1) * 32768, pos, mt, nt, tid);
            cp_commit();
            cp_wait<1>();
        } else {
            cp_wait<0>();
        }
        __syncthreads();

        uint32_t sAh = sb + buf * 32768;
        uint32_t sAl = sAh + 8192;
        uint32_t sBh = sAh + 16384;
        uint32_t sBl = sAh + 24576;

        #pragma unroll
        for (int ks = 0; ks < 2; ks++) {
            uint32_t ah[2][4], al[2][4];
            #pragma unroll
            for (int mi = 0; mi < 2; mi++) {
                int row = wm * 32 + mi * 16 + (lane & 15);
                int u = 2 * ks + (lane >> 4);
                uint32_t off = swz(row, u);
                ldm4(ah[mi], sAh + off);
                ldm4(al[mi], sAl + off);
            }
            uint32_t bh[8][2], bl[8][2];
            #pragma unroll
            for (int nj = 0; nj < 4; nj++) {
                int row = wn * 64 + nj * 16 + ((lane >> 4) << 3) + (lane & 7);
                int u = 2 * ks + ((lane >> 3) & 1);
                uint32_t off = swz(row, u);
                uint32_t r[4];
                ldm4(r, sBh + off);
                bh[2 * nj][0] = r[0]; bh[2 * nj][1] = r[1];
                bh[2 * nj + 1][0] = r[2]; bh[2 * nj + 1][1] = r[3];
                ldm4(r, sBl + off);
                bl[2 * nj][0] = r[0]; bl[2 * nj][1] = r[1];
                bl[2 * nj + 1][0] = r[2]; bl[2 * nj + 1][1] = r[3];
            }
            #pragma unroll
            for (int mi = 0; mi < 2; mi++)
                #pragma unroll
                for (int ni = 0; ni < 8; ni++) {
                    mma16816(acc[mi][ni], ah[mi], bh[ni]);
                    mma16816(acc[mi][ni], ah[mi], bl[ni]);
                    mma16816(acc[mi][ni], al[mi], bh[ni]);
                }
        }
        __syncthreads();
    }

    // epilogue: c-frag -> g_p[pos][m][n]
    #pragma unroll
    for (int mi = 0; mi < 2; mi++) {
        int m0 = mt * 128 + wm * 32 + mi * 16 + (lane >> 2);
        #pragma unroll
        for (int ni = 0; ni < 8; ni++) {
            int n = nt * 128 + wn * 64 + ni * 8 + (lane & 3) * 2;
            float* d0 = g_p + ((size_t)(pos * 256 + m0)) * 256 + n;
            d0[0] = acc[mi][ni][0];
            d0[1] = acc[mi][ni][1];
            float* d1 = d0 + 8 * 256;
            d1[0] = acc[mi][ni][2];
            d1[1] = acc[mi][ni][3];
        }
    }
}

// ------------------------------ squash -------------------------------------
// grid 1152 (i = cap*36+pos), block 256 (b).  g_p[pos][cap*8+d][b] -> g_u[i][b][d]
__global__ void squash_kernel(const float* __restrict__ pcb) {
    int i = blockIdx.x, b = threadIdx.x;
    int cap = i / 36, pos = i % 36;
    float v[8]; float sq = 0.f;
    #pragma unroll
    for (int d = 0; d < 8; d++) {
        float x = g_p[((size_t)(pos * 256 + cap * 8 + d)) * 256 + b] + pcb[cap * 8 + d];
        v[d] = x; sq += x * x;
    }
    float coef = sq / ((1.f + sq) * sqrtf(sq + 1e-8f));
    float* up = g_u + ((size_t)i * 256 + b) * 8;
    #pragma unroll
    for (int d = 0; d < 8; d++) up[d] = coef * v[d];
}

// ------------------------------ u_hat --------------------------------------
__global__ void uhat_kernel(const float* __restrict__ W) {
    __shared__ float Ws[8 * JO];
    int i = blockIdx.x, bgrp = blockIdx.y;
    int tid = threadIdx.x;
    for (int e = tid; e < 8 * JO; e += 320) Ws[e] = W[(size_t)i * 1280 + e];
    __syncthreads();
    int t = tid % JO, g = tid / JO;
    for (int bb = 0; bb < 16; bb++) {
        int b = bgrp * 32 + bb * 2 + g;
        const float* up = g_u + ((size_t)i * 256 + b) * 8;
        float a = 0.f;
        #pragma unroll
        for (int dd = 0; dd < 8; dd++) a += up[dd] * Ws[dd * JO + t];
        g_uhat[((size_t)b * NPRI + i) * JO + t] = a;
    }
}

// ------------------------------ routing ------------------------------------
__global__ void routing_kernel(float* __restrict__ out) {
    extern __shared__ float sm[];
    float* l    = sm;
    float* cpl  = sm + 11520;
    float* sred = sm + 23040;
    float* v    = sm + 23520;

    int b = blockIdx.x, tid = threadIdx.x;
    for (int e = tid; e < 11520; e += 480) l[e] = 0.f;
    __syncthreads();

    const float* uh = g_uhat + (size_t)b * NPRI * JO;
    int t = tid % JO, g = tid / JO;
    int j = t >> 4;

    for (int it = 0; it < 3; it++) {
        for (int row = tid; row < NPRI; row += 480) {
            float lv[10]; float m = -1e30f;
            #pragma unroll
            for (int jj = 0; jj < 10; jj++) { lv[jj] = l[row * 10 + jj]; m = fmaxf(m, lv[jj]); }
            float sum = 0.f;
            #pragma unroll
            for (int jj = 0; jj < 10; jj++) { lv[jj] = __expf(lv[jj] - m); sum += lv[jj]; }
            float r = 1.f / sum;
            #pragma unroll
            for (int jj = 0; jj < 10; jj++) cpl[row * 10 + jj] = lv[jj] * r;
        }
        __syncthreads();

        float s0 = 0.f, s1 = 0.f, s2 = 0.f, s3 = 0.f;
        int i0 = g * 384;
        for (int i = i0; i < i0 + 384; i += 4) {
            s0 += cpl[(i + 0) * 10 + j] * uh[(size_t)(i + 0) * JO + t];
            s1 += cpl[(i + 1) * 10 + j] * uh[(size_t)(i + 1) * JO + t];
            s2 += cpl[(i + 2) * 10 + j] * uh[(size_t)(i + 2) * JO + t];
            s3 += cpl[(i + 3) * 10 + j] * uh[(size_t)(i + 3) * JO + t];
        }
        sred[g * JO + t] = (s0 + s1) + (s2 + s3);
        __syncthreads();

        if (tid < JO) {
            float s = sred[t] + sred[JO + t] + sred[2 * JO + t];
            float sq = s * s;
            #pragma unroll
            for (int msk = 8; msk >= 1; msk >>= 1)
                sq += __shfl_xor_sync(0xffffffff, sq, msk);
            float coef = sq / ((1.f + sq) * sqrtf(sq + 1e-8f));
            float vv = coef * s;
            v[t] = vv;
            if (it == 2) out[b * JO + t] = vv;
        }
        __syncthreads();

        if (it < 2) {
            for (int pr = tid; pr < 11520; pr += 480) {
                int i = pr / 10, jj = pr % 10;
                const float* up = uh + (size_t)i * JO + jj * 16;
                const float* vp = v + jj * 16;
                float dot = 0.f;
                #pragma unroll
                for (int o = 0; o < 16; o++) dot += up[o] * vp[o];
                l[pr] += dot;
            }
            __syncthreads();
        }
    }
}

// ------------------------------ launch -------------------------------------
extern "C" void kernel_launch(void* const* d_in, const int* in_sizes, int n_in,
                              void* d_out, int out_size) {
    const float *x = nullptr, *w1 = nullptr, *b1 = nullptr;
    const float *wp = nullptr, *bp = nullptr, *Wd = nullptr;
    int n256 = 0;
    for (int i = 0; i < n_in; i++) {
        int s = in_sizes[i];
        const float* p = (const float*)d_in[i];
        if      (s == 200704)  x  = p;
        else if (s == 20736)   w1 = p;
        else if (s == 5308416) wp = p;
        else if (s == 1474560) Wd = p;
        else if (s == 256) { if (n256 == 0) b1 = p; else bp = p; n256++; }
    }
    if (!x  && n_in > 0) x  = (const float*)d_in[0];
    if (!w1 && n_in > 1) w1 = (const float*)d_in[1];
    if (!b1 && n_in > 2) b1 = (const float*)d_in[2];
    if (!wp && n_in > 3) wp = (const float*)d_in[3];
    if (!bp && n_in > 4) bp = (const float*)d_in[4];
    if (!Wd && n_in > 5) Wd = (const float*)d_in[5];

    cudaFuncSetAttribute(caps_gemm_kernel,
                         cudaFuncAttributeMaxDynamicSharedMemorySize, 65536);
    cudaFuncSetAttribute(routing_kernel,
                         cudaFuncAttributeMaxDynamicSharedMemorySize, 94720);

    repack_w1_kernel<<<81, 256>>>(w1);
    wsplit_kernel<<<256, 256>>>(wp);
    conv1_kernel<<<512, 256>>>(x, b1);
    hsplit_kernel<<<dim3(13, 8, 256), dim3(32, 8)>>>();
    caps_gemm_kernel<<<144, 256, 65536>>>();
    squash_kernel<<<1152, 256>>>(bp);
    uhat_kernel<<<dim3(1152, 8), 320>>>(Wd);
    routing_kernel<<<256, 480, 94720>>>((float*)d_out);
}